// round 11
// baseline (speedup 1.0000x reference)
#include <cuda_runtime.h>
#include <cfloat>

// 101-layer chain h <- relu(w*h + b), w > 0, collapses exactly to a single
// clamped affine, output-space form (division-free composition):
//   f(x) = max(S*x + O, F)
//   layer i: (S,O,F) = (w_i, b_i, 0)
//   g o f :  S' = Sg*Sf,  O' = Sg*Of + Og,  F' = max(Sg*Ff + Og, Fg)
//
// R11 = R9 chassis (flat, 64 B/thread, per-warp redundant shuffle scan, no
// barrier) with 256-BIT vector loads/stores (sm_100a+ ld/st.global.v8.f32,
// SASS LDG.E.256/STG.E.256): same bytes, half the LSU transactions and half
// the L1tex wavefront entries per byte.

struct __align__(32) f8 { float v[8]; };

__device__ __forceinline__ void ldg_v8(const float* p, float* r) {
    asm volatile(
        "ld.global.v8.f32 {%0, %1, %2, %3, %4, %5, %6, %7}, [%8];"
        : "=f"(r[0]), "=f"(r[1]), "=f"(r[2]), "=f"(r[3]),
          "=f"(r[4]), "=f"(r[5]), "=f"(r[6]), "=f"(r[7])
        : "l"(p));
}

__device__ __forceinline__ void stg_v8(float* p, const float* r) {
    asm volatile(
        "st.global.v8.f32 [%0], {%1, %2, %3, %4, %5, %6, %7, %8};"
        :: "l"(p),
           "f"(r[0]), "f"(r[1]), "f"(r[2]), "f"(r[3]),
           "f"(r[4]), "f"(r[5]), "f"(r[6]), "f"(r[7])
        : "memory");
}

__global__ __launch_bounds__(256)
void fused_flat_v8_kernel(const float* __restrict__ x,
                          float* __restrict__ out,
                          const float* __restrict__ w,
                          const float* __restrict__ b,
                          int n_layers, int n8, int n) {
    const int tid  = threadIdx.x;
    const int lane = tid & 31;
    // block tile: 512 float8s (16 KB); 2 float8 per thread
    const long i0 = (long)blockIdx.x * 512 + tid;
    const long i1 = i0 + 256;

    // Prefetch both 256-bit loads FIRST: DRAM latency overlaps the scan.
    const bool ok0 = (i0 < n8);
    const bool ok1 = (i1 < n8);
    float a0[8], a1[8];
    if (ok0) ldg_v8(x + i0 * 8, a0);
    if (ok1) ldg_v8(x + i1 * 8, a1);

    // ---- per-warp division-free shuffle scan (up to 128 layers) ----
    float S = 1.0f, O = 0.0f, F = -FLT_MAX;
    #pragma unroll
    for (int k = 0; k < 4; ++k) {
        const int idx = 4 * lane + k;             // independent loads
        if (idx < n_layers) {
            const float wi = w[idx];              // layer: (wi, bi, 0)
            const float bi = b[idx];
            F = fmaxf(fmaf(wi, F, bi), 0.0f);
            O = fmaf(wi, O, bi);
            S = wi * S;
        }
    }
    #pragma unroll
    for (int d = 1; d < 32; d <<= 1) {
        const float Sp = __shfl_up_sync(0xffffffffu, S, d);
        const float Op = __shfl_up_sync(0xffffffffu, O, d);
        const float Fp = __shfl_up_sync(0xffffffffu, F, d);
        if (lane >= d) {
            F = fmaxf(fmaf(S, Fp, O), F);
            O = fmaf(S, Op, O);
            S = S * Sp;
        }
    }
    S = __shfl_sync(0xffffffffu, S, 31);
    O = __shfl_sync(0xffffffffu, O, 31);
    F = __shfl_sync(0xffffffffu, F, 31);

    if (ok0) {
        float r[8];
        #pragma unroll
        for (int k = 0; k < 8; ++k) r[k] = fmaxf(fmaf(S, a0[k], O), F);
        stg_v8(out + i0 * 8, r);
    }
    if (ok1) {
        float r[8];
        #pragma unroll
        for (int k = 0; k < 8; ++k) r[k] = fmaxf(fmaf(S, a1[k], O), F);
        stg_v8(out + i1 * 8, r);
    }

    // scalar tail (n % 8 != 0) — negligible
    if (blockIdx.x == 0 && tid == 0) {
        for (long j = (long)n8 * 8; j < n; ++j) {
            out[j] = fmaxf(fmaf(S, x[j], O), F);
        }
    }
}

extern "C" void kernel_launch(void* const* d_in, const int* in_sizes, int n_in,
                              void* d_out, int out_size) {
    const float* x = (const float*)d_in[0];
    const float* w = (const float*)d_in[1];
    const float* b = (const float*)d_in[2];
    float* out = (float*)d_out;

    const int n        = in_sizes[0];
    const int n_layers = in_sizes[1];
    const int n8       = n / 8;

    const int threads = 256;
    const int blocks  = (n8 + 511) / 512;   // 2 float8 per thread

    fused_flat_v8_kernel<<<blocks, threads>>>(
        x, out, w, b, n_layers, n8, n);
}

// round 12
// speedup vs baseline: 1.0522x; 1.0522x over previous
#include <cuda_runtime.h>
#include <cfloat>

// FINAL (converged) — R7 build.
//
// 101-layer chain h <- relu(w*h + b), w > 0, collapses exactly to
//   f(x) = S * max(x, C) + O.
// Prefix triples (S, C, O) compose associatively:
//   (g o f): S = Sg*Sf,  C = max(Cf, (Cg - Of)/Sf),  O = Sg*Of + Og.
//
// Structure: flat grid, 4 float4 per thread (contiguous 1024-float4 block
// tile), EVERY warp computes the 101-layer scan redundantly via shuffles —
// no __syncthreads, no shared memory. The ~500-cycle scan hides entirely
// under each thread's 4 prefetched DRAM loads (~577 cyc), and each warp
// proceeds to its stores independently.
//
// Convergence evidence (R6-R11): tile size (2/4/8), barrier vs barrier-free,
// divide vs division-free scan, __stcs stores, and 256-bit v8 ld/st ALL land
// at 36.5 +/- 0.15 us kernel @ ~5.8 TB/s — the chip's effective mixed r+w
// fp32 stream ceiling. Traffic (128 MiB in + 128 MiB out) is irreducible.

__global__ __launch_bounds__(256)
void fused_flat4_ws_kernel(const float4* __restrict__ x4,
                           float4* __restrict__ o4,
                           const float* __restrict__ w,
                           const float* __restrict__ b,
                           int n_layers, int n4, int n,
                           const float* __restrict__ x,
                           float* __restrict__ out) {
    const int tid  = threadIdx.x;
    const int lane = tid & 31;
    const int base = blockIdx.x * 1024 + tid;

    // Prefetch all four elements FIRST: DRAM latency overlaps the scan.
    float4 v0, v1, v2, v3;
    const bool ok0 = (base       < n4);
    const bool ok1 = (base + 256 < n4);
    const bool ok2 = (base + 512 < n4);
    const bool ok3 = (base + 768 < n4);
    if (ok0) v0 = x4[base];
    if (ok1) v1 = x4[base + 256];
    if (ok2) v2 = x4[base + 512];
    if (ok3) v3 = x4[base + 768];

    // ---- per-warp shuffle scan over up to 128 layers (no barrier) ----
    float S = 1.0f, C = -FLT_MAX, O = 0.0f;
    #pragma unroll
    for (int k = 0; k < 4; ++k) {
        const int idx = 4 * lane + k;             // independent loads
        if (idx < n_layers) {
            const float wi = w[idx];
            const float bi = b[idx];
            const float Cl = __fdividef(-bi, wi);
            C = fmaxf(C, __fdividef(Cl - O, S));
            S = wi * S;
            O = fmaf(wi, O, bi);
        }
    }
    #pragma unroll
    for (int d = 1; d < 32; d <<= 1) {
        const float Sp = __shfl_up_sync(0xffffffffu, S, d);
        const float Cp = __shfl_up_sync(0xffffffffu, C, d);
        const float Op = __shfl_up_sync(0xffffffffu, O, d);
        if (lane >= d) {
            C = fmaxf(Cp, __fdividef(C - Op, Sp));
            O = fmaf(S, Op, O);   // uses pre-update S
            S = S * Sp;
        }
    }
    // broadcast lane 31's inclusive result to the whole warp
    S = __shfl_sync(0xffffffffu, S, 31);
    C = __shfl_sync(0xffffffffu, C, 31);
    O = __shfl_sync(0xffffffffu, O, 31);

    float4 r;
    if (ok0) {
        r.x = fmaf(S, fmaxf(v0.x, C), O); r.y = fmaf(S, fmaxf(v0.y, C), O);
        r.z = fmaf(S, fmaxf(v0.z, C), O); r.w = fmaf(S, fmaxf(v0.w, C), O);
        o4[base] = r;
    }
    if (ok1) {
        r.x = fmaf(S, fmaxf(v1.x, C), O); r.y = fmaf(S, fmaxf(v1.y, C), O);
        r.z = fmaf(S, fmaxf(v1.z, C), O); r.w = fmaf(S, fmaxf(v1.w, C), O);
        o4[base + 256] = r;
    }
    if (ok2) {
        r.x = fmaf(S, fmaxf(v2.x, C), O); r.y = fmaf(S, fmaxf(v2.y, C), O);
        r.z = fmaf(S, fmaxf(v2.z, C), O); r.w = fmaf(S, fmaxf(v2.w, C), O);
        o4[base + 512] = r;
    }
    if (ok3) {
        r.x = fmaf(S, fmaxf(v3.x, C), O); r.y = fmaf(S, fmaxf(v3.y, C), O);
        r.z = fmaf(S, fmaxf(v3.z, C), O); r.w = fmaf(S, fmaxf(v3.w, C), O);
        o4[base + 768] = r;
    }

    // scalar tail (n % 4 != 0) — negligible
    if (blockIdx.x == 0 && tid == 0) {
        for (int j = n4 * 4; j < n; ++j) {
            out[j] = fmaf(S, fmaxf(x[j], C), O);
        }
    }
}

extern "C" void kernel_launch(void* const* d_in, const int* in_sizes, int n_in,
                              void* d_out, int out_size) {
    const float* x = (const float*)d_in[0];
    const float* w = (const float*)d_in[1];
    const float* b = (const float*)d_in[2];
    float* out = (float*)d_out;

    const int n        = in_sizes[0];
    const int n_layers = in_sizes[1];
    const int n4       = n / 4;

    const int threads = 256;
    const int blocks  = (n4 + 1023) / 1024;   // 4 float4 per thread

    fused_flat4_ws_kernel<<<blocks, threads>>>(
        (const float4*)x, (float4*)out, w, b, n_layers, n4, n, x, out);
}